// round 17
// baseline (speedup 1.0000x reference)
#include <cuda_runtime.h>
#include <cstdint>

#define N_ 8
#define C_ 128
#define H_ 64
#define W_ 64
#define HW 4096

typedef unsigned long long u64;

// scratch (no allocs allowed)
__device__ float g_t7 [N_ * C_ * HW];            // 16 MB
__device__ float g_y  [N_ * C_ * HW];            // 16 MB
__device__ float g_up [N_ * 32 * C_ * C_];       // 16 MB split-K partials
__device__ float g_u  [N_ * C_ * C_];            // 512 KB (transposed: [n][ci][co])
__device__ float g_p7h[C_ * C_];                 // p7 tf32-hi  [co][ci]
__device__ float g_p7l[C_ * C_];                 // p7 residual [co][ci]
__device__ float2 g_whl[4 * 32 * 32 * 28];       // conv W (hi,lo) [g][ci][cin][28tap]

// ---- helpers ---------------------------------------------------------------
__device__ __forceinline__ u64 pack2(float a, float b) {
    u64 r;
    asm("mov.b64 %0, {%1, %2};" : "=l"(r) : "f"(a), "f"(b));
    return r;
}
__device__ __forceinline__ void fma2(u64& d, u64 a, u64 b) {
    asm("fma.rn.f32x2 %0, %1, %2, %0;" : "+l"(d) : "l"(a), "l"(b));
}
__device__ __forceinline__ float lo2(u64 v) { return __uint_as_float((unsigned)v); }
__device__ __forceinline__ float hi2(u64 v) { return __uint_as_float((unsigned)(v >> 32)); }

__device__ __forceinline__ uint32_t s2u(const void* p) {
    return (uint32_t)__cvta_generic_to_shared(p);
}
__device__ __forceinline__ void cpa16(uint32_t dst, const void* src) {
    asm volatile("cp.async.cg.shared.global [%0], [%1], 16;" :: "r"(dst), "l"(src));
}
__device__ __forceinline__ void cpa_commit() {
    asm volatile("cp.async.commit_group;" ::: "memory");
}
__device__ __forceinline__ void cpa_wait0() {
    asm volatile("cp.async.wait_group 0;" ::: "memory");
}
// cvt.rna.tf32.f32 needs a .b32 destination (ptxas rejects .f32 dst).
__device__ __forceinline__ uint32_t tf32_bits(float v) {
    uint32_t h;
    asm("cvt.rna.tf32.f32 %0, %1;" : "=r"(h) : "f"(v));
    return h;
}
__device__ __forceinline__ void tf32_split(float v, float& hf, float& lf) {
    uint32_t hb = tf32_bits(v);
    hf = __uint_as_float(hb);
    float lo = v - hf;
    lf = __uint_as_float(tf32_bits(lo));
}
// D += A(16x8,row) * B(8x8,col)  tf32
__device__ __forceinline__ void mma_tf32(float* c, uint32_t a0, uint32_t a1,
                                         uint32_t a2, uint32_t a3,
                                         uint32_t b0, uint32_t b1) {
    asm volatile(
        "mma.sync.aligned.m16n8k8.row.col.f32.tf32.tf32.f32 "
        "{%0,%1,%2,%3}, {%4,%5,%6,%7}, {%8,%9}, {%0,%1,%2,%3};"
        : "+f"(c[0]), "+f"(c[1]), "+f"(c[2]), "+f"(c[3])
        : "r"(a0), "r"(a1), "r"(a2), "r"(a3), "r"(b0), "r"(b1));
}

// ---------------------------------------------------------------------------
// K0a: pre-split p7 into tf32 hi/lo ([co][ci] row-major)
// ---------------------------------------------------------------------------
__global__ void k0_prep(const float* __restrict__ p7)
{
    int idx = blockIdx.x * 256 + threadIdx.x;   // 16384
    float h, l;
    tf32_split(p7[idx], h, l);
    g_p7h[idx] = h;
    g_p7l[idx] = l;
}

// ---------------------------------------------------------------------------
// K0b: pre-split conv weights into interleaved (hi,lo), taps padded 21->28.
// g_whl[((g*32+ci)*32 + cin)*28 + tap] = (hi, lo) of W(g,ci,tap,cin)
// ---------------------------------------------------------------------------
__global__ void k0_wprep(const float* __restrict__ p10)
{
    int idx = blockIdx.x * 256 + threadIdx.x;   // 114688
    if (idx >= 4 * 32 * 32 * 28) return;
    int tap = idx % 28;
    int cin = (idx / 28) % 32;
    int cig = idx / 896;                        // g*32 + ci
    float v = (tap < 21) ? p10[((size_t)cig * 21 + tap) * 32 + cin] : 0.f;
    float h, l;
    tf32_split(v, h, l);
    g_whl[idx] = make_float2(h, l);
}

// ---------------------------------------------------------------------------
// K1 (mma.sync tf32, pipelined): t7 = p7 @ relu(x)   [unchanged]
// ---------------------------------------------------------------------------
__global__ void __launch_bounds__(256) k1_mma(const float* __restrict__ x)
{
    extern __shared__ __align__(16) float sm[];
    const int t = threadIdx.x;
    const int pt = blockIdx.x, n = blockIdx.y;
    const int p0 = pt * 128;
    const int wid = t >> 5, lane = t & 31;
    const int g4 = lane >> 2, l4 = lane & 3;
    const int wco = wid * 16;
    const float* xn = x + (size_t)n * C_ * HW;

    float c[16][4];
#pragma unroll
    for (int i = 0; i < 16; i++)
#pragma unroll
        for (int j = 0; j < 4; j++) c[i][j] = 0.f;

    float4 bx[2];
    auto ldgB = [&](int sub) {
        const int ci0 = sub * 16;
#pragma unroll
        for (int k = 0; k < 2; k++) {
            int fi = t + k * 256;
            int ci = fi >> 5, pq = (fi & 31) * 4;
            bx[k] = *reinterpret_cast<const float4*>(
                &xn[(size_t)(ci0 + ci) * HW + p0 + pq]);
        }
    };
    auto cpaA = [&](int sub, int b) {
        const int ci0 = sub * 16;
        float* Ah = sm + b * 2560;
        float* Al = sm + 5120 + b * 2560;
#pragma unroll
        for (int k = 0; k < 2; k++) {
            int fi = t + k * 256;
            int co = fi >> 2, q = (fi & 3) * 4;
            cpa16(s2u(&Ah[co * 20 + q]), &g_p7h[co * 128 + ci0 + q]);
            cpa16(s2u(&Al[co * 20 + q]), &g_p7l[co * 128 + ci0 + q]);
        }
        cpa_commit();
    };
    auto stsB = [&](int b) {
        float* Bh = sm + 10240 + b * 2176;
        float* Bl = sm + 14592 + b * 2176;
#pragma unroll
        for (int k = 0; k < 2; k++) {
            int fi = t + k * 256;
            int ci = fi >> 5, pq = (fi & 31) * 4;
            float4 vh, vl;
            tf32_split(fmaxf(bx[k].x, 0.f), vh.x, vl.x);
            tf32_split(fmaxf(bx[k].y, 0.f), vh.y, vl.y);
            tf32_split(fmaxf(bx[k].z, 0.f), vh.z, vl.z);
            tf32_split(fmaxf(bx[k].w, 0.f), vh.w, vl.w);
            *reinterpret_cast<float4*>(&Bh[ci * 136 + pq]) = vh;
            *reinterpret_cast<float4*>(&Bl[ci * 136 + pq]) = vl;
        }
    };

    ldgB(0);
    cpaA(0, 0);
    stsB(0);
    cpa_wait0();
    __syncthreads();

    for (int sub = 0; sub < 8; sub++) {
        const int cur = sub & 1;
        if (sub < 7) {
            ldgB(sub + 1);
            cpaA(sub + 1, cur ^ 1);
        }
        const float* Ah = sm + cur * 2560;
        const float* Al = sm + 5120 + cur * 2560;
        const float* Bh = sm + 10240 + cur * 2176;
        const float* Bl = sm + 14592 + cur * 2176;
#pragma unroll
        for (int ks = 0; ks < 2; ks++) {
            const int k0 = ks * 8;
            const float* Ab  = &Ah[(wco + g4) * 20 + k0 + l4];
            const float* Alb = &Al[(wco + g4) * 20 + k0 + l4];
            uint32_t ah0 = __float_as_uint(Ab[0]);
            uint32_t ah1 = __float_as_uint(Ab[8 * 20]);
            uint32_t ah2 = __float_as_uint(Ab[4]);
            uint32_t ah3 = __float_as_uint(Ab[8 * 20 + 4]);
            uint32_t al0 = __float_as_uint(Alb[0]);
            uint32_t al1 = __float_as_uint(Alb[8 * 20]);
            uint32_t al2 = __float_as_uint(Alb[4]);
            uint32_t al3 = __float_as_uint(Alb[8 * 20 + 4]);
#pragma unroll
            for (int tile = 0; tile < 16; tile++) {
                const float* Bb  = &Bh[(k0 + l4) * 136 + tile * 8 + g4];
                const float* Blb = &Bl[(k0 + l4) * 136 + tile * 8 + g4];
                uint32_t bh0 = __float_as_uint(Bb[0]);
                uint32_t bh1 = __float_as_uint(Bb[4 * 136]);
                uint32_t bl0 = __float_as_uint(Blb[0]);
                uint32_t bl1 = __float_as_uint(Blb[4 * 136]);
                mma_tf32(c[tile], ah0, ah1, ah2, ah3, bh0, bh1);
                mma_tf32(c[tile], ah0, ah1, ah2, ah3, bl0, bl1);
                mma_tf32(c[tile], al0, al1, al2, al3, bh0, bh1);
            }
        }
        if (sub < 7) {
            stsB(cur ^ 1);
            cpa_wait0();
            __syncthreads();
        }
    }

    float* t7n = g_t7 + (size_t)n * C_ * HW;
    const int r0 = wco + g4, r1 = wco + g4 + 8;
#pragma unroll
    for (int tile = 0; tile < 16; tile++) {
        const int p = p0 + tile * 8 + l4 * 2;
        *reinterpret_cast<float2*>(&t7n[(size_t)r0 * HW + p]) =
            make_float2(c[tile][0], c[tile][1]);
        *reinterpret_cast<float2*>(&t7n[(size_t)r1 * HW + p]) =
            make_float2(c[tile][2], c[tile][3]);
    }
}

// ---------------------------------------------------------------------------
// K2 (mma.sync tf32 implicit GEMM, v2): grouped 3x7 conv.
// (hi,lo) interleaved float2 smem; hoisted patch index math.
// Block (hs, g, n): M=32 cin, N=512 (warp=h row, 8 n-tiles), K=32ci x 24 taps.
// ---------------------------------------------------------------------------
__global__ void __launch_bounds__(256, 2) k2_mma(const float* __restrict__ x)
{
    __shared__ __align__(16) float2 Whl[2][32 * 30];  // W (hi,lo) [cin][tap] pitch 30
    __shared__ __align__(16) float2 Phl[2][11 * 77];  // patch (hi,lo) [pr][pc] pitch 77

    const int t = threadIdx.x;
    const int hs = blockIdx.x, g = blockIdx.y, n = blockIdx.z;
    const int h0 = hs * 8;
    const int wid = t >> 5, lane = t & 31;      // wid = local h row
    const int g4 = lane >> 2, l4 = lane & 3;

    float c[2][8][4];
#pragma unroll
    for (int mt = 0; mt < 2; mt++)
#pragma unroll
        for (int nt = 0; nt < 8; nt++)
#pragma unroll
            for (int j = 0; j < 4; j++) c[mt][nt][j] = 0.f;

    // hoisted patch fill indices (4 elements / thread, 770 total)
    const float* xg = x + (size_t)(n * C_ + g * 32) * HW;
    bool pvalid[4];
    int goff[4], soff[4];
#pragma unroll
    for (int k = 0; k < 4; k++) {
        int i = t + k * 256;
        if (i < 770) {
            int pr = i / 70, pc = i - pr * 70;
            int hg = h0 - 1 + pr, wg = pc - 3;
            pvalid[k] = ((unsigned)hg < 64u) && ((unsigned)wg < 64u);
            goff[k] = hg * 64 + wg;
            soff[k] = pr * 77 + pc;
        } else {
            pvalid[k] = false;
            goff[k] = 0;
            soff[k] = -1;
        }
    }

    auto fillW = [&](int ci, int b) {
        const float2* wsrc = g_whl + (size_t)(g * 32 + ci) * 32 * 28;
        for (int i = t; i < 448; i += 256) {
            int row = i / 14, off = (i - row * 14) * 2;
            cpa16(s2u(&Whl[b][row * 30 + off]), wsrc + row * 28 + off);
        }
        cpa_commit();
    };

    float pv[4];
    auto ldgP = [&](int ci) {
        const float* xc = xg + (size_t)ci * HW;
#pragma unroll
        for (int k = 0; k < 4; k++)
            pv[k] = pvalid[k] ? __ldg(&xc[goff[k]]) : 0.f;
    };
    auto stsP = [&](int b) {
#pragma unroll
        for (int k = 0; k < 4; k++) {
            if (soff[k] >= 0) {
                float h, l;
                tf32_split(pv[k], h, l);
                Phl[b][soff[k]] = make_float2(h, l);
            }
        }
    };

    ldgP(0);
    fillW(0, 0);
    stsP(0);
    cpa_wait0();
    __syncthreads();

    for (int ci = 0; ci < 32; ci++) {
        const int cur = ci & 1;
        if (ci < 31) {
            ldgP(ci + 1);
            fillW(ci + 1, cur ^ 1);
        }
        const float2* W = Whl[cur];
        const float2* P = Phl[cur];
#pragma unroll
        for (int c3 = 0; c3 < 3; c3++) {
            const int k0 = c3 * 8;
            uint32_t ah[2][4], al[2][4];
#pragma unroll
            for (int mt = 0; mt < 2; mt++) {
                float2 va0 = W[(mt * 16 + g4) * 30 + k0 + l4];
                float2 va1 = W[(mt * 16 + g4 + 8) * 30 + k0 + l4];
                float2 va2 = W[(mt * 16 + g4) * 30 + k0 + l4 + 4];
                float2 va3 = W[(mt * 16 + g4 + 8) * 30 + k0 + l4 + 4];
                ah[mt][0] = __float_as_uint(va0.x); al[mt][0] = __float_as_uint(va0.y);
                ah[mt][1] = __float_as_uint(va1.x); al[mt][1] = __float_as_uint(va1.y);
                ah[mt][2] = __float_as_uint(va2.x); al[mt][2] = __float_as_uint(va2.y);
                ah[mt][3] = __float_as_uint(va3.x); al[mt][3] = __float_as_uint(va3.y);
            }
            const int tap0 = k0 + l4, tap1 = tap0 + 4;
            const int di0 = tap0 / 7, dj0 = tap0 - di0 * 7;
            const int di1 = tap1 / 7, dj1 = tap1 - di1 * 7;
            const int base0 = (wid + di0) * 77 + g4 + dj0;
            const int base1 = (wid + di1) * 77 + g4 + dj1;
#pragma unroll
            for (int nt = 0; nt < 8; nt++) {
                float2 vb0 = P[base0 + nt * 8];
                float2 vb1 = P[base1 + nt * 8];
                uint32_t bh0 = __float_as_uint(vb0.x), bl0 = __float_as_uint(vb0.y);
                uint32_t bh1 = __float_as_uint(vb1.x), bl1 = __float_as_uint(vb1.y);
#pragma unroll
                for (int mt = 0; mt < 2; mt++) {
                    mma_tf32(c[mt][nt], ah[mt][0], ah[mt][1], ah[mt][2], ah[mt][3], bh0, bh1);
                    mma_tf32(c[mt][nt], ah[mt][0], ah[mt][1], ah[mt][2], ah[mt][3], bl0, bl1);
                    mma_tf32(c[mt][nt], al[mt][0], al[mt][1], al[mt][2], al[mt][3], bh0, bh1);
                }
            }
        }
        if (ci < 31) {
            stsP(cur ^ 1);
            cpa_wait0();
            __syncthreads();
        }
    }

    // epilogue: y[n][g*32+cin][h0+wid][w]
    const int h = h0 + wid;
#pragma unroll
    for (int mt = 0; mt < 2; mt++) {
        const int cin0 = g * 32 + mt * 16 + g4;
        float* y0 = g_y + ((size_t)(n * C_ + cin0) * 64 + h) * 64;
        float* y1 = g_y + ((size_t)(n * C_ + cin0 + 8) * 64 + h) * 64;
#pragma unroll
        for (int nt = 0; nt < 8; nt++) {
            const int w = nt * 8 + l4 * 2;
            *reinterpret_cast<float2*>(&y0[w]) = make_float2(c[mt][nt][0], c[mt][nt][1]);
            *reinterpret_cast<float2*>(&y1[w]) = make_float2(c[mt][nt][2], c[mt][nt][3]);
        }
    }
}

// ---------------------------------------------------------------------------
// K3 (mma.sync tf32, pipelined): u_part = t1 @ y^T   [unchanged]
// ---------------------------------------------------------------------------
__global__ void __launch_bounds__(256) k3_mma(const float* __restrict__ x,
                                              const float* __restrict__ p1)
{
    extern __shared__ __align__(16) float sm[];
    const int t = threadIdx.x;
    const int kc = blockIdx.x, n = blockIdx.y;
    const int wid = t >> 5, lane = t & 31;
    const int g4 = lane >> 2, l4 = lane & 3;
    const int wco = wid * 16;

    const int p0 = kc * 128;
    const float* xn = x   + (size_t)n * C_ * HW;
    const float* yn = g_y + (size_t)n * C_ * HW;

    float c[16][4];
#pragma unroll
    for (int i = 0; i < 16; i++)
#pragma unroll
        for (int j = 0; j < 4; j++) c[i][j] = 0.f;

    float4 ax[2], ay[2];
    float sA[2];
    auto ldg = [&](int sub) {
        const int pb = p0 + sub * 16;
        const int h = pb >> 6;
#pragma unroll
        for (int k = 0; k < 2; k++) {
            int fi = t + k * 256;
            int row = fi >> 2, q = (fi & 3) * 4;
            sA[k] = p1[row * 64 + h] * (1.f / 64.f);
            ax[k] = *reinterpret_cast<const float4*>(&xn[(size_t)row * HW + pb + q]);
            ay[k] = *reinterpret_cast<const float4*>(&yn[(size_t)row * HW + pb + q]);
        }
    };
    auto sts = [&](int b) {
        float* Ah = sm + b * 2560;
        float* Al = sm + 5120 + b * 2560;
        float* Bh = sm + 10240 + b * 2560;
        float* Bl = sm + 15360 + b * 2560;
#pragma unroll
        for (int k = 0; k < 2; k++) {
            int fi = t + k * 256;
            int row = fi >> 2, q = (fi & 3) * 4;
            float4 vh, vl;
            tf32_split(sA[k] * ax[k].x, vh.x, vl.x);
            tf32_split(sA[k] * ax[k].y, vh.y, vl.y);
            tf32_split(sA[k] * ax[k].z, vh.z, vl.z);
            tf32_split(sA[k] * ax[k].w, vh.w, vl.w);
            *reinterpret_cast<float4*>(&Ah[row * 20 + q]) = vh;
            *reinterpret_cast<float4*>(&Al[row * 20 + q]) = vl;
            tf32_split(ay[k].x, vh.x, vl.x);
            tf32_split(ay[k].y, vh.y, vl.y);
            tf32_split(ay[k].z, vh.z, vl.z);
            tf32_split(ay[k].w, vh.w, vl.w);
            *reinterpret_cast<float4*>(&Bh[row * 20 + q]) = vh;
            *reinterpret_cast<float4*>(&Bl[row * 20 + q]) = vl;
        }
    };

    ldg(0);
    sts(0);
    __syncthreads();

    for (int sub = 0; sub < 8; sub++) {
        const int cur = sub & 1;
        if (sub < 7) ldg(sub + 1);
        const float* Ah = sm + cur * 2560;
        const float* Al = sm + 5120 + cur * 2560;
        const float* Bh = sm + 10240 + cur * 2560;
        const float* Bl = sm + 15360 + cur * 2560;
#pragma unroll
        for (int ks = 0; ks < 2; ks++) {
            const int k0 = ks * 8;
            const float* Ab  = &Ah[(wco + g4) * 20 + k0 + l4];
            const float* Alb = &Al[(wco + g4) * 20 + k0 + l4];
            uint32_t ah0 = __float_as_uint(Ab[0]);
            uint32_t ah1 = __float_as_uint(Ab[8 * 20]);
            uint32_t ah2 = __float_as_uint(Ab[4]);
            uint32_t ah3 = __float_as_uint(Ab[8 * 20 + 4]);
            uint32_t al0 = __float_as_uint(Alb[0]);
            uint32_t al1 = __float_as_uint(Alb[8 * 20]);
            uint32_t al2 = __float_as_uint(Alb[4]);
            uint32_t al3 = __float_as_uint(Alb[8 * 20 + 4]);
#pragma unroll
            for (int tile = 0; tile < 16; tile++) {
                const float* Bb  = &Bh[(tile * 8 + g4) * 20 + k0 + l4];
                const float* Blb = &Bl[(tile * 8 + g4) * 20 + k0 + l4];
                uint32_t bh0 = __float_as_uint(Bb[0]);
                uint32_t bh1 = __float_as_uint(Bb[4]);
                uint32_t bl0 = __float_as_uint(Blb[0]);
                uint32_t bl1 = __float_as_uint(Blb[4]);
                mma_tf32(c[tile], ah0, ah1, ah2, ah3, bh0, bh1);
                mma_tf32(c[tile], ah0, ah1, ah2, ah3, bl0, bl1);
                mma_tf32(c[tile], al0, al1, al2, al3, bh0, bh1);
            }
        }
        if (sub < 7) {
            sts(cur ^ 1);
            __syncthreads();
        }
    }

    float* up = g_up + ((size_t)(n * 32 + kc)) * C_ * C_;
    const int r0 = wco + g4, r1 = wco + g4 + 8;
#pragma unroll
    for (int tile = 0; tile < 16; tile++) {
        const int cix = tile * 8 + l4 * 2;
        *reinterpret_cast<float2*>(&up[(size_t)r0 * 128 + cix]) =
            make_float2(c[tile][0], c[tile][1]);
        *reinterpret_cast<float2*>(&up[(size_t)r1 * 128 + cix]) =
            make_float2(c[tile][2], c[tile][3]);
    }
}

// K3b: reduce 32 split-K partials; write u transposed: g_u[n][ci][co]
__global__ void k3_red()
{
    int o = blockIdx.x * 256 + threadIdx.x;   // 131072
    int n = o >> 14, r = o & 16383;
    float s = 0.f;
#pragma unroll
    for (int kc = 0; kc < 32; kc++)
        s += g_up[(((size_t)(n * 32 + kc)) << 14) + r];
    int co = r >> 7, ci = r & 127;
    g_u[((size_t)n << 14) + ci * 128 + co] = s;
}

// ---------------------------------------------------------------------------
// K4: out = max( s3 * sum_ci u[n,co,ci]*t2[ci,p],  x[co,p] - 0.2*sum_jj t7 taps )
// ---------------------------------------------------------------------------
__global__ void k4_out(const float* __restrict__ x, const float* __restrict__ p1,
                       float* __restrict__ out)
{
    __shared__ __align__(16) float xs [128 * 64];     // t2[ci][w], later t7[co][w]
    __shared__ __align__(16) float as2[2][2048];      // u chunks [kk=ci][co]
    const int row = blockIdx.x, n = blockIdx.y;
    const int t = threadIdx.x;  // 128
    const int tx = t & 7, ty = t >> 3;
    const float* xn = x + (size_t)n * C_ * HW + row * 64;
    const float* un = g_u + ((size_t)n << 14);

#pragma unroll
    for (int r = 0; r < 4; r++)
        cpa16(s2u(&as2[0][r * 512 + t * 4]), &un[r * 512 + t * 4]);
    cpa_commit();

#pragma unroll
    for (int r = 0; r < 16; r++) {
        int idx4 = r * 512 + t * 4;
        int ci = idx4 >> 6, w = idx4 & 63;
        float s = 1.f + p1[ci * 64 + row];
        float4 v = *reinterpret_cast<const float4*>(&xn[(size_t)ci * HW + w]);
        v.x *= s; v.y *= s; v.z *= s; v.w *= s;
        *reinterpret_cast<float4*>(&xs[idx4]) = v;
    }

    u64 acc[4][8];
#pragma unroll
    for (int p = 0; p < 4; p++)
#pragma unroll
        for (int j = 0; j < 8; j++) acc[p][j] = 0ull;

    cpa_wait0();
    __syncthreads();

    for (int kb = 0; kb < 8; kb++) {
        const int cur = kb & 1;
        if (kb < 7) {
#pragma unroll
            for (int r = 0; r < 4; r++)
                cpa16(s2u(&as2[cur ^ 1][r * 512 + t * 4]),
                      &un[(kb + 1) * 2048 + r * 512 + t * 4]);
            cpa_commit();
        }
#pragma unroll
        for (int kk = 0; kk < 16; kk++) {
            int k = kb * 16 + kk;
            float4 b0 = *reinterpret_cast<const float4*>(&xs[k * 64 + tx * 8]);
            float4 b1 = *reinterpret_cast<const float4*>(&xs[k * 64 + tx * 8 + 4]);
            u64 a0 = *reinterpret_cast<const u64*>(&as2[cur][kk * 128 + ty * 8 + 0]);
            u64 a1 = *reinterpret_cast<const u64*>(&as2[cur][kk * 128 + ty * 8 + 2]);
            u64 a2 = *reinterpret_cast<const u64*>(&as2[cur][kk * 128 + ty * 8 + 4]);
            u64 a3 = *reinterpret_cast<const u64*>(&as2[cur][kk * 128 + ty * 8 + 6]);
            u64 bb[8];
            bb[0] = pack2(b0.x, b0.x); bb[1] = pack2(b0.y, b0.y);
            bb[2] = pack2(b0.z, b0.z); bb[3] = pack2(b0.w, b0.w);
            bb[4] = pack2(b1.x, b1.x); bb[5] = pack2(b1.y, b1.y);
            bb[6] = pack2(b1.z, b1.z); bb[7] = pack2(b1.w, b1.w);
#pragma unroll
            for (int j = 0; j < 8; j++) {
                fma2(acc[0][j], a0, bb[j]);
                fma2(acc[1][j], a1, bb[j]);
                fma2(acc[2][j], a2, bb[j]);
                fma2(acc[3][j], a3, bb[j]);
            }
        }
        if (kb < 7) { cpa_wait0(); __syncthreads(); }
    }

    // epilogue: reuse xs for t7[n,:,row,:]
    __syncthreads();
#pragma unroll
    for (int r = 0; r < 16; r++) {
        int idx4 = r * 512 + t * 4;
        int ci = idx4 >> 6, w = idx4 & 63;
        *reinterpret_cast<float4*>(&xs[idx4]) =
            *reinterpret_cast<const float4*>(
                &g_t7[((size_t)n * C_ + ci) * HW + row * 64 + w]);
    }
    __syncthreads();

    const float s3 = 0.01928793f;    // 1/sqrt(2688)
#pragma unroll
    for (int p = 0; p < 4; p++) {
#pragma unroll
        for (int half = 0; half < 2; half++) {
            int co = ty * 8 + 2 * p + half;
            const float* xr = xn + (size_t)co * HW;
            float4 xv0 = *reinterpret_cast<const float4*>(&xr[tx * 8]);
            float4 xv1 = *reinterpret_cast<const float4*>(&xr[tx * 8 + 4]);
            float xv[8] = {xv0.x, xv0.y, xv0.z, xv0.w, xv1.x, xv1.y, xv1.z, xv1.w};
            float res[8];
#pragma unroll
            for (int j = 0; j < 8; j++) {
                int pp = tx * 8 + j;
                float a = half ? hi2(acc[p][j]) : lo2(acc[p][j]);
                float sum = 0.f;
#pragma unroll
                for (int jj = 0; jj < 5; jj++) {
                    int wp = pp + 3 * jj - 6;
                    if ((unsigned)wp < 64u) sum += xs[co * 64 + wp];
                }
                float t12 = xv[j] - 0.2f * sum;
                res[j] = fmaxf(s3 * a, t12);
            }
            float* orow = out + ((size_t)n * C_ + co) * HW + row * 64;
            *reinterpret_cast<float4*>(&orow[tx * 8]) =
                make_float4(res[0], res[1], res[2], res[3]);
            *reinterpret_cast<float4*>(&orow[tx * 8 + 4]) =
                make_float4(res[4], res[5], res[6], res[7]);
        }
    }
}

// ---------------------------------------------------------------------------
extern "C" void kernel_launch(void* const* d_in, const int* in_sizes, int n_in,
                              void* d_out, int out_size)
{
    const float* x   = (const float*)d_in[0];   // (8,128,64,64)
    const float* p1w = (const float*)d_in[1];   // (1,128,64,1)
    const float* p7w = (const float*)d_in[2];   // (128,128)
    const float* p10 = (const float*)d_in[3];   // (2688,32)
    float* out = (float*)d_out;

    const int k1_smem = 18944 * 4;   // 75776 B
    const int k3_smem = 20480 * 4;   // 81920 B
    cudaFuncSetAttribute(k1_mma, cudaFuncAttributeMaxDynamicSharedMemorySize, k1_smem);
    cudaFuncSetAttribute(k3_mma, cudaFuncAttributeMaxDynamicSharedMemorySize, k3_smem);

    k0_prep <<<64, 256>>>(p7w);
    k0_wprep<<<448, 256>>>(p10);
    k1_mma  <<<dim3(32, 8), 256, k1_smem>>>(x);
    k2_mma  <<<dim3(8, 4, 8), 256>>>(x);
    k3_mma  <<<dim3(32, 8), 256, k3_smem>>>(x, p1w);
    k3_red  <<<512, 256>>>();
    k4_out  <<<dim3(64, 8), 128>>>(x, p1w, out);
}